// round 8
// baseline (speedup 1.0000x reference)
#include <cuda_runtime.h>
#include <math.h>
#include <string.h>

#define B_ 4
#define S_ 4096
#define H_ 2048
#define E_ 16
#define ED_ 512
#define H4 (H_/4)          // 512 float4 (or ulonglong2) per row
#define NBLK_A 512
#define ROWS_PER_BLK_A 32
#define BLKS_PER_BATCH (NBLK_A / B_)   // 128
#define NBLK_B 512

// ---------------- device scratch (written fresh every launch) ----------------
__device__ float g_part[NBLK_A * H_];   // per-block LN partial sums (4 MB)
__device__ float g_qi[B_ * H_];         // query_input
__device__ float g_lf[E_ * H_];         // layer_features
__device__ float g_attp[NBLK_B * B_ * E_]; // per-block attention partials
__device__ int   g_ctr;                 // zero-init at load; reset by epilogue

__device__ __forceinline__ float warp_sum(float v) {
#pragma unroll
    for (int o = 16; o > 0; o >>= 1) v += __shfl_xor_sync(0xffffffffu, v, o);
    return v;
}

// packed f32x2 fma: d = a*b + c (elementwise on the two packed floats)
__device__ __forceinline__ unsigned long long ffma2(unsigned long long a,
                                                    unsigned long long b,
                                                    unsigned long long c) {
    unsigned long long d;
    asm("fma.rn.f32x2 %0, %1, %2, %3;" : "=l"(d) : "l"(a), "l"(b), "l"(c));
    return d;
}
__device__ __forceinline__ float pairsum(unsigned long long v) {
    float2 f; memcpy(&f, &v, 8);
    return f.x + f.y;
}

// ---------------- Kernel A: LayerNorm + mean over S (partials) ----------------
// 4 warps per row, 2 rows in flight per block (rg = warp>>2), next-row loads
// prefetched, ONE barrier per row-pair iteration (parity-buffered s_ms).
__global__ void __launch_bounds__(256, 4) kA(const float* __restrict__ hid) {
    __shared__ float2 s_ms[2][8];        // [parity][warp] (sum, sumsq)
    __shared__ float4 s_acc[4][128];     // rg=1 accumulator staging (8 KB)
    const int warp = threadIdx.x >> 5, lane = threadIdx.x & 31;
    const int qt = warp & 3;             // quarter of the row
    const int rg = warp >> 2;            // which of the 2 in-flight rows
    const size_t row0 = (size_t)blockIdx.x * ROWS_PER_BLK_A;
    const int colbase = qt * 128 + lane; // float4 index within row

    const float4* base = reinterpret_cast<const float4*>(hid);
    float4 v[4], acc[4];
#pragma unroll
    for (int i = 0; i < 4; i++) acc[i] = make_float4(0.f, 0.f, 0.f, 0.f);
    {   // preload first row of this row-group
        const float4* p = base + (row0 + rg) * H4 + colbase;
#pragma unroll
        for (int i = 0; i < 4; i++) v[i] = p[i * 32];
    }

    for (int it = 0; it < 16; it++) {
        // prefetch next iteration's row (last iter: reload same row, harmless)
        const size_t nrow = row0 + ((it < 15) ? (size_t)(it * 2 + 2 + rg)
                                              : (size_t)(it * 2 + rg));
        const float4* p = base + nrow * H4 + colbase;
        float4 n0 = p[0], n1 = p[32], n2 = p[64], n3 = p[96];

        float s = 0.f, s2 = 0.f;
#pragma unroll
        for (int i = 0; i < 4; i++) {
            s  += v[i].x + v[i].y + v[i].z + v[i].w;
            s2 += v[i].x * v[i].x + v[i].y * v[i].y
                + v[i].z * v[i].z + v[i].w * v[i].w;
        }
        s = warp_sum(s); s2 = warp_sum(s2);
        if (lane == 0) s_ms[it & 1][warp] = make_float2(s, s2);
        __syncthreads();
        // read my row-group's 4 partials as 2x LDS.128
        const float4* sm = reinterpret_cast<const float4*>(&s_ms[it & 1][rg * 4]);
        float4 p0 = sm[0], p1 = sm[1];
        const float S  = p0.x + p0.z + p1.x + p1.z;
        const float S2 = p0.y + p0.w + p1.y + p1.w;
        const float mu = S * (1.f / H_);
        const float rr = rsqrtf(S2 * (1.f / H_) - mu * mu + 1e-5f);
#pragma unroll
        for (int i = 0; i < 4; i++) {
            acc[i].x += (v[i].x - mu) * rr;
            acc[i].y += (v[i].y - mu) * rr;
            acc[i].z += (v[i].z - mu) * rr;
            acc[i].w += (v[i].w - mu) * rr;
        }
        v[0] = n0; v[1] = n1; v[2] = n2; v[3] = n3;
    }
    // combine the two row-groups and write g_part
    if (rg == 1) {
#pragma unroll
        for (int i = 0; i < 4; i++) s_acc[qt][i * 32 + lane] = acc[i];
    }
    __syncthreads();
    if (rg == 0) {
        float4* out4 = reinterpret_cast<float4*>(g_part) + (size_t)blockIdx.x * H4;
#pragma unroll
        for (int i = 0; i < 4; i++) {
            float4 b = s_acc[qt][i * 32 + lane];
            out4[colbase + i * 32] = make_float4(acc[i].x + b.x, acc[i].y + b.y,
                                                 acc[i].z + b.z, acc[i].w + b.w);
        }
    }
}

// ---------------- Kernel B0: reduce partials -> query_input; build lf --------
__global__ void __launch_bounds__(256) kB0(const float* __restrict__ le,
                                           const float* __restrict__ ce,
                                           const float* __restrict__ gamma,
                                           const float* __restrict__ beta,
                                           const int* __restrict__ curp) {
    const int blk = blockIdx.x;
    if (blk < 64) {
        __shared__ float4 s_q[8][32];
        const int b = blk >> 4, chunk = blk & 15;
        const int lane = threadIdx.x & 31, csub = threadIdx.x >> 5;
        const int h4 = chunk * 32 + lane;
        const float4* gp = reinterpret_cast<const float4*>(g_part);
        size_t base = ((size_t)(b * BLKS_PER_BATCH + csub * 16)) * H4 + h4;
        float4 s = make_float4(0.f, 0.f, 0.f, 0.f);
#pragma unroll
        for (int c = 0; c < 16; c++) {
            float4 t = gp[base + (size_t)c * H4];
            s.x += t.x; s.y += t.y; s.z += t.z; s.w += t.w;
        }
        s_q[csub][lane] = s;
        __syncthreads();
        if (threadIdx.x < 32) {
            float4 t = s_q[0][lane];
#pragma unroll
            for (int q = 1; q < 8; q++) {
                float4 u = s_q[q][lane];
                t.x += u.x; t.y += u.y; t.z += u.z; t.w += u.w;
            }
            const int cur = *curp;
            float4 g4 = reinterpret_cast<const float4*>(gamma)[h4];
            float4 b4 = reinterpret_cast<const float4*>(beta)[h4];
            float4 l4 = reinterpret_cast<const float4*>(le)[cur * H4 + h4];
            float4 r;
            r.x = l4.x + g4.x * (t.x * (1.f / S_)) + b4.x;
            r.y = l4.y + g4.y * (t.y * (1.f / S_)) + b4.y;
            r.z = l4.z + g4.z * (t.z * (1.f / S_)) + b4.z;
            r.w = l4.w + g4.w * (t.w * (1.f / S_)) + b4.w;
            reinterpret_cast<float4*>(g_qi)[b * H4 + h4] = r;
        }
    } else {
        int idx = (blk - 64) * 256 + threadIdx.x;  // 0..8191 float4
        float4 a = reinterpret_cast<const float4*>(le)[idx];
        float4 c = reinterpret_cast<const float4*>(ce)[idx];
        reinterpret_cast<float4*>(g_lf)[idx] =
            make_float4(a.x + c.x, a.y + c.y, a.z + c.z, a.w + c.w);
    }
}

// ---------------- Kernel B: fused q/k GEMV + attention partials + epilogue ----
// 512 blocks x 128 threads; warp owns ONE output column j; packed f32x2 FMA.
__global__ void __launch_bounds__(128) kB(const float* __restrict__ Wq,
                                          const float* __restrict__ bq,
                                          const float* __restrict__ Wk,
                                          const float* __restrict__ bk,
                                          const float* __restrict__ spatial,
                                          const float* __restrict__ edge,
                                          const int* __restrict__ curp,
                                          const int* __restrict__ avail,
                                          float* __restrict__ out) {
    __shared__ float s_attp[4][B_ * E_];
    __shared__ float s_red[2][B_ * E_];
    __shared__ float s_att[B_ * E_];
    __shared__ float s_w[ED_];
    __shared__ float s_eb[E_];
    __shared__ float s_sb[E_];
    __shared__ int   s_last;

    const int tid = threadIdx.x, warp = tid >> 5, lane = tid & 31;
    const int j = blockIdx.x * 4 + warp;         // 0..2047

    unsigned long long aq[B_], ak[E_];
#pragma unroll
    for (int b = 0; b < B_; b++) aq[b] = 0ull;
#pragma unroll
    for (int e = 0; e < E_; e++) ak[e] = 0ull;

    const ulonglong2* wqp = reinterpret_cast<const ulonglong2*>(Wq) + (size_t)j * H4;
    const ulonglong2* wkp = reinterpret_cast<const ulonglong2*>(Wk) + (size_t)j * H4;
    const ulonglong2* qi = reinterpret_cast<const ulonglong2*>(g_qi);
    const ulonglong2* lf = reinterpret_cast<const ulonglong2*>(g_lf);

#pragma unroll 4
    for (int t = 0; t < 16; t++) {
        const int idx = t * 32 + lane;
        ulonglong2 a = wqp[idx];
        ulonglong2 c = wkp[idx];
#pragma unroll
        for (int b = 0; b < B_; b++) {
            ulonglong2 x = qi[b * H4 + idx];
            aq[b] = ffma2(a.x, x.x, aq[b]);
            aq[b] = ffma2(a.y, x.y, aq[b]);
        }
#pragma unroll
        for (int e = 0; e < E_; e++) {
            ulonglong2 x = lf[e * H4 + idx];
            ak[e] = ffma2(c.x, x.x, ak[e]);
            ak[e] = ffma2(c.y, x.y, ak[e]);
        }
    }
    float q[B_], k[E_];
    const float bqj = bq[j], bkj = bk[j];
#pragma unroll
    for (int b = 0; b < B_; b++) q[b] = warp_sum(pairsum(aq[b])) + bqj;
#pragma unroll
    for (int e = 0; e < E_; e++) k[e] = warp_sum(pairsum(ak[e])) + bkj;

    if (lane == 0) {
        const float inv_sqrt_h = rsqrtf((float)H_);
#pragma unroll
        for (int b = 0; b < B_; b++)
#pragma unroll
            for (int e = 0; e < E_; e++)
                s_attp[warp][b * E_ + e] = (q[b] * k[e]) * inv_sqrt_h;
    }
    __syncthreads();
    if (tid < B_ * E_) {
        float s = s_attp[0][tid] + s_attp[1][tid] + s_attp[2][tid] + s_attp[3][tid];
        g_attp[blockIdx.x * (B_ * E_) + tid] = s;
    }
    __threadfence();
    __syncthreads();
    if (tid == 0) {
        int old = atomicAdd(&g_ctr, 1);
        s_last = (old == NBLK_B - 1) ? 1 : 0;
    }
    __syncthreads();
    if (!s_last) return;

    // ================= epilogue (last block only, 128 threads) =================
    const int cur = *curp;
    {
        int o = tid & 63, qc = tid >> 6;   // 2 chunks of 256 blocks
        float s = 0.f;
#pragma unroll 8
        for (int c = 0; c < 256; c++) s += g_attp[(qc * 256 + c) * (B_ * E_) + o];
        s_red[qc][o] = s;
    }
    for (int h = tid; h < ED_; h += 128) {
        float a = 0.f;
#pragma unroll
        for (int i = 0; i < E_; i++) {
            int d = abs(i - cur);
            float rm = (float)avail[i] * ((i != cur) ? 1.f : 0.f) * (1.f / (float)max(d, 1));
            a += rm * edge[i * ED_ + h];
        }
        s_w[h] = a;
    }
    if (tid < E_) s_sb[tid] = spatial[abs(tid - cur)];
    __syncthreads();
    if (tid < B_ * E_) s_att[tid] = s_red[0][tid] + s_red[1][tid];

    for (int jj = 0; jj < 4; jj++) {
        int je = warp * 4 + jj;
        float s = 0.f;
#pragma unroll
        for (int t = 0; t < 16; t++) s += s_w[t * 32 + lane] * edge[je * ED_ + t * 32 + lane];
        s = warp_sum(s);
        if (lane == 0) s_eb[je] = s;
    }
    __syncthreads();

    if (warp == 0) {
        float av = (lane < E_) ? (float)avail[lane] : 0.f;
        float num_avail = warp_sum(av);
        float tprob = 1.f / num_avail;
        float logt = logf(tprob);
        float klacc = 0.f;
        int nidx = 0;
        for (int b = 0; b < B_; b++) {
            float sc = -1e30f;
            if (lane < E_) {
                bool ok = (avail[lane] > 0);
                sc = s_att[b * E_ + lane] + s_sb[lane] + s_eb[lane];
                sc = ok ? sc : -1e9f;
            }
            float m = sc;
#pragma unroll
            for (int o = 8; o > 0; o >>= 1) m = fmaxf(m, __shfl_xor_sync(0xffffffffu, m, o, 16));
            float ex = (lane < E_) ? __expf(sc - m) : 0.f;
            float sum = ex;
#pragma unroll
            for (int o = 8; o > 0; o >>= 1) sum += __shfl_xor_sync(0xffffffffu, sum, o, 16);
            float p = (lane < E_) ? (ex / sum) : 0.f;
            if (lane < E_) out[1 + b * E_ + lane] = p;
            float ps = fmaxf(p, 1e-10f);
            if (lane < E_) klacc += tprob * (logt - logf(ps));
            if (b == 0) {
                float pm = (lane < E_) ? p : -1.f;
                float mm = pm;
#pragma unroll
                for (int o = 16; o > 0; o >>= 1) mm = fmaxf(mm, __shfl_xor_sync(0xffffffffu, mm, o));
                unsigned bal = __ballot_sync(0xffffffffu, pm == mm);
                nidx = __ffs(bal) - 1;
            }
        }
        float kl = warp_sum(klacc);
        if (lane == 0) {
            out[0] = (kl / (float)B_) * 0.01f;
            out[1 + B_ * E_] = (float)nidx;
            g_ctr = 0;   // reset for next graph replay
        }
    }
}

// ---------------- launch ----------------
extern "C" void kernel_launch(void* const* d_in, const int* in_sizes, int n_in,
                              void* d_out, int out_size) {
    const float* hid     = (const float*)d_in[0];
    const float* le      = (const float*)d_in[1];
    const float* ce      = (const float*)d_in[2];
    const float* spatial = (const float*)d_in[3];
    const float* edge    = (const float*)d_in[4];
    const float* gamma   = (const float*)d_in[5];
    const float* beta    = (const float*)d_in[6];
    const float* Wq      = (const float*)d_in[7];
    const float* bq      = (const float*)d_in[8];
    const float* Wk      = (const float*)d_in[9];
    const float* bk      = (const float*)d_in[10];
    // d_in[11], d_in[12] (Wv, bv) intentionally unused: v is dead in the reference
    const int*   curp    = (const int*)d_in[13];
    const int*   avail   = (const int*)d_in[14];
    float* out = (float*)d_out;

    kA<<<NBLK_A, 256>>>(hid);
    kB0<<<96, 256>>>(le, ce, gamma, beta, curp);
    kB<<<NBLK_B, 128>>>(Wq, bq, Wk, bk, spatial, edge, curp, avail, out);
}

// round 9
// speedup vs baseline: 1.0492x; 1.0492x over previous
#include <cuda_runtime.h>
#include <math.h>
#include <string.h>

#define B_ 4
#define S_ 4096
#define H_ 2048
#define E_ 16
#define ED_ 512
#define H4 (H_/4)          // 512 16-byte units per row
#define NBLK_A 1024
#define ROWS_PER_BLK_A 16
#define BLKS_PER_BATCH (NBLK_A / B_)   // 256
#define NBLK_B 128

typedef unsigned long long ull;

// ---------------- device scratch (written fresh every launch) ----------------
__device__ float g_part[NBLK_A * H_];   // per-block LN partial sums (8 MB)
__device__ float g_qi[B_ * H_];         // query_input
__device__ float g_lf[E_ * H_];         // layer_features
__device__ float g_attp[NBLK_B * B_ * E_]; // per-block attention partials
__device__ int   g_ctr;                 // zero-init at load; reset by epilogue

__device__ __forceinline__ float warp_sum(float v) {
#pragma unroll
    for (int o = 16; o > 0; o >>= 1) v += __shfl_xor_sync(0xffffffffu, v, o);
    return v;
}
// packed f32x2 helpers
__device__ __forceinline__ ull ffma2(ull a, ull b, ull c) {
    ull d;
    asm("fma.rn.f32x2 %0, %1, %2, %3;" : "=l"(d) : "l"(a), "l"(b), "l"(c));
    return d;
}
__device__ __forceinline__ ull add2(ull a, ull b) {
    ull d;
    asm("add.rn.f32x2 %0, %1, %2;" : "=l"(d) : "l"(a), "l"(b));
    return d;
}
__device__ __forceinline__ float pairsum(ull v) {
    float2 f; memcpy(&f, &v, 8);
    return f.x + f.y;
}
__device__ __forceinline__ ull pack2(float f) {
    float2 t = make_float2(f, f);
    ull r; memcpy(&r, &t, 8);
    return r;
}

// ---------------- Kernel A: LayerNorm + mean over S (partials) ----------------
// 4 warps per row, 2 rows in flight per block, 1 barrier/iter, f32x2 math.
__global__ void __launch_bounds__(256, 4) kA(const float* __restrict__ hid) {
    __shared__ float2 s_ms[2][8];           // [parity][warp] (sum, sumsq)
    __shared__ ulonglong2 s_acc[4][128];    // rg=1 accumulator staging (8 KB)
    const int warp = threadIdx.x >> 5, lane = threadIdx.x & 31;
    const int qt = warp & 3;                // quarter of the row
    const int rg = warp >> 2;               // which of the 2 in-flight rows
    const size_t row0 = (size_t)blockIdx.x * ROWS_PER_BLK_A;
    const int colbase = qt * 128 + lane;    // 16B-unit index within row

    const ulonglong2* base = reinterpret_cast<const ulonglong2*>(hid);
    const ulonglong2* p = base + (row0 + rg) * H4 + colbase;

    ulonglong2 v[4];
    ull acc[8];
#pragma unroll
    for (int i = 0; i < 8; i++) acc[i] = 0ull;
#pragma unroll
    for (int i = 0; i < 4; i++) v[i] = p[i * 32];

    for (int it = 0; it < 8; it++) {
        // prefetch next iteration's row (last iter re-reads same row; harmless)
        const ulonglong2* pn = p + ((it < 7) ? 2 * H4 : 0);
        ulonglong2 n0 = pn[0], n1 = pn[32], n2 = pn[64], n3 = pn[96];

        ull sp = 0ull, sq = 0ull;
#pragma unroll
        for (int i = 0; i < 4; i++) {
            sp = add2(sp, v[i].x); sp = add2(sp, v[i].y);
            sq = ffma2(v[i].x, v[i].x, sq);
            sq = ffma2(v[i].y, v[i].y, sq);
        }
        float s = warp_sum(pairsum(sp));
        float s2 = warp_sum(pairsum(sq));
        if (lane == 0) s_ms[it & 1][warp] = make_float2(s, s2);
        __syncthreads();
        const float4* sm = reinterpret_cast<const float4*>(&s_ms[it & 1][rg * 4]);
        float4 p0 = sm[0], p1 = sm[1];
        const float S  = p0.x + p0.z + p1.x + p1.z;
        const float S2 = p0.y + p0.w + p1.y + p1.w;
        const float mu = S * (1.f / H_);
        const float rr = rsqrtf(S2 * (1.f / H_) - mu * mu + 1e-5f);
        const ull rr2 = pack2(rr);
        const ull c2 = pack2(-mu * rr);
#pragma unroll
        for (int i = 0; i < 4; i++) {
            acc[2 * i]     = add2(ffma2(v[i].x, rr2, acc[2 * i]), c2);
            acc[2 * i + 1] = add2(ffma2(v[i].y, rr2, acc[2 * i + 1]), c2);
        }
        v[0] = n0; v[1] = n1; v[2] = n2; v[3] = n3;
        p = pn;
    }
    // combine the two row-groups and write g_part
    if (rg == 1) {
#pragma unroll
        for (int i = 0; i < 4; i++)
            s_acc[qt][i * 32 + lane] = make_ulonglong2(acc[2 * i], acc[2 * i + 1]);
    }
    __syncthreads();
    if (rg == 0) {
        ulonglong2* out = reinterpret_cast<ulonglong2*>(g_part) + (size_t)blockIdx.x * H4;
#pragma unroll
        for (int i = 0; i < 4; i++) {
            ulonglong2 b = s_acc[qt][i * 32 + lane];
            out[colbase + i * 32] =
                make_ulonglong2(add2(acc[2 * i], b.x), add2(acc[2 * i + 1], b.y));
        }
    }
}

// ---------------- Kernel B0: reduce partials -> query_input; build lf --------
__global__ void __launch_bounds__(256) kB0(const float* __restrict__ le,
                                           const float* __restrict__ ce,
                                           const float* __restrict__ gamma,
                                           const float* __restrict__ beta,
                                           const int* __restrict__ curp) {
    const int blk = blockIdx.x;
    if (blk < 64) {
        __shared__ float4 s_q[8][32];
        const int b = blk >> 4, chunk = blk & 15;
        const int lane = threadIdx.x & 31, csub = threadIdx.x >> 5;
        const int h4 = chunk * 32 + lane;
        const float4* gp = reinterpret_cast<const float4*>(g_part);
        size_t base = ((size_t)(b * BLKS_PER_BATCH + csub * 32)) * H4 + h4;
        float4 s = make_float4(0.f, 0.f, 0.f, 0.f);
#pragma unroll
        for (int c = 0; c < 32; c++) {
            float4 t = gp[base + (size_t)c * H4];
            s.x += t.x; s.y += t.y; s.z += t.z; s.w += t.w;
        }
        s_q[csub][lane] = s;
        __syncthreads();
        if (threadIdx.x < 32) {
            float4 t = s_q[0][lane];
#pragma unroll
            for (int q = 1; q < 8; q++) {
                float4 u = s_q[q][lane];
                t.x += u.x; t.y += u.y; t.z += u.z; t.w += u.w;
            }
            const int cur = *curp;
            float4 g4 = reinterpret_cast<const float4*>(gamma)[h4];
            float4 b4 = reinterpret_cast<const float4*>(beta)[h4];
            float4 l4 = reinterpret_cast<const float4*>(le)[cur * H4 + h4];
            float4 r;
            r.x = l4.x + g4.x * (t.x * (1.f / S_)) + b4.x;
            r.y = l4.y + g4.y * (t.y * (1.f / S_)) + b4.y;
            r.z = l4.z + g4.z * (t.z * (1.f / S_)) + b4.z;
            r.w = l4.w + g4.w * (t.w * (1.f / S_)) + b4.w;
            reinterpret_cast<float4*>(g_qi)[b * H4 + h4] = r;
        }
    } else {
        int idx = (blk - 64) * 256 + threadIdx.x;  // 0..8191 float4
        float4 a = reinterpret_cast<const float4*>(le)[idx];
        float4 c = reinterpret_cast<const float4*>(ce)[idx];
        reinterpret_cast<float4*>(g_lf)[idx] =
            make_float4(a.x + c.x, a.y + c.y, a.z + c.z, a.w + c.w);
    }
}

// ---------------- Kernel B: fused q/k GEMV with smem-staged x + epilogue ------
// 128 blocks x 256 threads (8 warps); warp owns 2 columns; x (qi+lf) staged in
// smem per block in 4 chunks -> kills L2 x-amplification.
__global__ void __launch_bounds__(256) kB(const float* __restrict__ Wq,
                                          const float* __restrict__ bq,
                                          const float* __restrict__ Wk,
                                          const float* __restrict__ bk,
                                          const float* __restrict__ spatial,
                                          const float* __restrict__ edge,
                                          const int* __restrict__ curp,
                                          const int* __restrict__ avail,
                                          float* __restrict__ out) {
    __shared__ ulonglong2 s_x[20 * 128];   // 40 KB: chunk of 20 rows x 512 floats
    __shared__ float s_attp[8][B_ * E_];
    __shared__ float s_red[4][B_ * E_];
    __shared__ float s_att[B_ * E_];
    __shared__ float s_w[ED_];
    __shared__ float s_eb[E_];
    __shared__ float s_sb[E_];
    __shared__ int   s_last;

    const int tid = threadIdx.x, warp = tid >> 5, lane = tid & 31;
    const int j0 = blockIdx.x * 16 + warp * 2;   // 2 columns per warp

    ull aq0[B_], aq1[B_], ak0[E_], ak1[E_];
#pragma unroll
    for (int b = 0; b < B_; b++) { aq0[b] = 0ull; aq1[b] = 0ull; }
#pragma unroll
    for (int e = 0; e < E_; e++) { ak0[e] = 0ull; ak1[e] = 0ull; }

    const float4* qi4 = reinterpret_cast<const float4*>(g_qi);
    const float4* lf4 = reinterpret_cast<const float4*>(g_lf);
    const ulonglong2* wq0 = reinterpret_cast<const ulonglong2*>(Wq) + (size_t)j0 * H4;
    const ulonglong2* wq1 = wq0 + H4;
    const ulonglong2* wk0 = reinterpret_cast<const ulonglong2*>(Wk) + (size_t)j0 * H4;
    const ulonglong2* wk1 = wk0 + H4;
    float4* s_x4 = reinterpret_cast<float4*>(s_x);

    for (int c = 0; c < 4; c++) {
        // cooperative stage: 20 rows x 128 float4 = 2560 float4, 10 per thread
#pragma unroll
        for (int i = 0; i < 10; i++) {
            int idx = i * 256 + tid;
            int row = idx >> 7, col = idx & 127;
            float4 t = (row < B_) ? qi4[row * H4 + c * 128 + col]
                                  : lf4[(row - B_) * H4 + c * 128 + col];
            s_x4[idx] = t;
        }
        __syncthreads();
#pragma unroll
        for (int t = 0; t < 4; t++) {
            const int idx = t * 32 + lane;
            const int gidx = c * 128 + idx;
            ulonglong2 a0 = wq0[gidx], a1 = wq1[gidx];
            ulonglong2 c0 = wk0[gidx], c1 = wk1[gidx];
#pragma unroll
            for (int b = 0; b < B_; b++) {
                ulonglong2 x = s_x[b * 128 + idx];
                aq0[b] = ffma2(a0.x, x.x, aq0[b]); aq0[b] = ffma2(a0.y, x.y, aq0[b]);
                aq1[b] = ffma2(a1.x, x.x, aq1[b]); aq1[b] = ffma2(a1.y, x.y, aq1[b]);
            }
#pragma unroll
            for (int e = 0; e < E_; e++) {
                ulonglong2 x = s_x[(B_ + e) * 128 + idx];
                ak0[e] = ffma2(c0.x, x.x, ak0[e]); ak0[e] = ffma2(c0.y, x.y, ak0[e]);
                ak1[e] = ffma2(c1.x, x.x, ak1[e]); ak1[e] = ffma2(c1.y, x.y, ak1[e]);
            }
        }
        __syncthreads();
    }
    // reductions + biases
    float q0[B_], q1[B_], k0[E_], k1[E_];
    const float bq0 = bq[j0], bq1 = bq[j0 + 1];
    const float bk0 = bk[j0], bk1 = bk[j0 + 1];
#pragma unroll
    for (int b = 0; b < B_; b++) {
        q0[b] = warp_sum(pairsum(aq0[b])) + bq0;
        q1[b] = warp_sum(pairsum(aq1[b])) + bq1;
    }
#pragma unroll
    for (int e = 0; e < E_; e++) {
        k0[e] = warp_sum(pairsum(ak0[e])) + bk0;
        k1[e] = warp_sum(pairsum(ak1[e])) + bk1;
    }
    if (lane == 0) {
        const float inv_sqrt_h = rsqrtf((float)H_);
#pragma unroll
        for (int b = 0; b < B_; b++)
#pragma unroll
            for (int e = 0; e < E_; e++)
                s_attp[warp][b * E_ + e] = (q0[b] * k0[e] + q1[b] * k1[e]) * inv_sqrt_h;
    }
    __syncthreads();
    if (tid < B_ * E_) {
        float s = 0.f;
#pragma unroll
        for (int w = 0; w < 8; w++) s += s_attp[w][tid];
        g_attp[blockIdx.x * (B_ * E_) + tid] = s;
    }
    __threadfence();
    __syncthreads();
    if (tid == 0) {
        int old = atomicAdd(&g_ctr, 1);
        s_last = (old == NBLK_B - 1) ? 1 : 0;
    }
    __syncthreads();
    if (!s_last) return;

    // ================= epilogue (last block only, 256 threads) =================
    const int cur = *curp;
    {
        int o = tid & 63, qc = tid >> 6;   // 4 chunks of 32 blocks
        float s = 0.f;
#pragma unroll 8
        for (int c = 0; c < 32; c++) s += g_attp[(qc * 32 + c) * (B_ * E_) + o];
        s_red[qc][o] = s;
    }
    for (int h = tid; h < ED_; h += 256) {
        float a = 0.f;
#pragma unroll
        for (int i = 0; i < E_; i++) {
            int d = abs(i - cur);
            float rm = (float)avail[i] * ((i != cur) ? 1.f : 0.f) * (1.f / (float)max(d, 1));
            a += rm * edge[i * ED_ + h];
        }
        s_w[h] = a;
    }
    if (tid < E_) s_sb[tid] = spatial[abs(tid - cur)];
    __syncthreads();
    if (tid < B_ * E_)
        s_att[tid] = s_red[0][tid] + s_red[1][tid] + s_red[2][tid] + s_red[3][tid];

    // edge_bias[j] = w . edge[j,:]; 8 warps x 2 outputs
    for (int jj = 0; jj < 2; jj++) {
        int je = warp * 2 + jj;
        float s = 0.f;
#pragma unroll
        for (int t = 0; t < 16; t++) s += s_w[t * 32 + lane] * edge[je * ED_ + t * 32 + lane];
        s = warp_sum(s);
        if (lane == 0) s_eb[je] = s;
    }
    __syncthreads();

    if (warp == 0) {
        float av = (lane < E_) ? (float)avail[lane] : 0.f;
        float num_avail = warp_sum(av);
        float tprob = 1.f / num_avail;
        float logt = logf(tprob);
        float klacc = 0.f;
        int nidx = 0;
        for (int b = 0; b < B_; b++) {
            float sc = -1e30f;
            if (lane < E_) {
                bool ok = (avail[lane] > 0);
                sc = s_att[b * E_ + lane] + s_sb[lane] + s_eb[lane];
                sc = ok ? sc : -1e9f;
            }
            float m = sc;
#pragma unroll
            for (int o = 8; o > 0; o >>= 1) m = fmaxf(m, __shfl_xor_sync(0xffffffffu, m, o, 16));
            float ex = (lane < E_) ? __expf(sc - m) : 0.f;
            float sum = ex;
#pragma unroll
            for (int o = 8; o > 0; o >>= 1) sum += __shfl_xor_sync(0xffffffffu, sum, o, 16);
            float p = (lane < E_) ? (ex / sum) : 0.f;
            if (lane < E_) out[1 + b * E_ + lane] = p;
            float ps = fmaxf(p, 1e-10f);
            if (lane < E_) klacc += tprob * (logt - logf(ps));
            if (b == 0) {
                float pm = (lane < E_) ? p : -1.f;
                float mm = pm;
#pragma unroll
                for (int o = 16; o > 0; o >>= 1) mm = fmaxf(mm, __shfl_xor_sync(0xffffffffu, mm, o));
                unsigned bal = __ballot_sync(0xffffffffu, pm == mm);
                nidx = __ffs(bal) - 1;
            }
        }
        float kl = warp_sum(klacc);
        if (lane == 0) {
            out[0] = (kl / (float)B_) * 0.01f;
            out[1 + B_ * E_] = (float)nidx;
            g_ctr = 0;   // reset for next graph replay
        }
    }
}

// ---------------- launch ----------------
extern "C" void kernel_launch(void* const* d_in, const int* in_sizes, int n_in,
                              void* d_out, int out_size) {
    const float* hid     = (const float*)d_in[0];
    const float* le      = (const float*)d_in[1];
    const float* ce      = (const float*)d_in[2];
    const float* spatial = (const float*)d_in[3];
    const float* edge    = (const float*)d_in[4];
    const float* gamma   = (const float*)d_in[5];
    const float* beta    = (const float*)d_in[6];
    const float* Wq      = (const float*)d_in[7];
    const float* bq      = (const float*)d_in[8];
    const float* Wk      = (const float*)d_in[9];
    const float* bk      = (const float*)d_in[10];
    // d_in[11], d_in[12] (Wv, bv) intentionally unused: v is dead in the reference
    const int*   curp    = (const int*)d_in[13];
    const int*   avail   = (const int*)d_in[14];
    float* out = (float*)d_out;

    kA<<<NBLK_A, 256>>>(hid);
    kB0<<<96, 256>>>(le, ce, gamma, beta, curp);
    kB<<<NBLK_B, 256>>>(Wq, bq, Wk, bk, spatial, edge, curp, avail, out);
}